// round 4
// baseline (speedup 1.0000x reference)
#include <cuda_runtime.h>
#include <math.h>

#define BDIM 16
#define GDIM 2048
#define DDIM 256
#define NHEADS 8
#define HEADDIM 32
#define FFND 1024
#define LAYERS 4
#define ROWS (BDIM*GDIM)   // 32768

// Scratch (device globals; no runtime allocation allowed)
__device__ float g_h [ROWS*DDIM];
__device__ float g_hn[ROWS*DDIM];
__device__ float g_q [ROWS*DDIM];
__device__ float g_k [ROWS*DDIM];
__device__ float g_v [ROWS*DDIM];
__device__ float g_mid[ROWS*FFND];

// ---------------------------------------------------------------------------
// Embedding: h = gene_emb + [sin(x*inv_freq), cos(x*inv_freq)] (0 where masked)
// ---------------------------------------------------------------------------
__global__ void embed_kernel(const float* __restrict__ x,
                             const float* __restrict__ gene_emb,
                             const float* __restrict__ inv_freq,
                             float* __restrict__ h) {
    int row = blockIdx.x;            // 0..ROWS-1
    int g   = row % GDIM;
    int i   = threadIdx.x;           // 0..127
    float xv = x[row];
    float fr = xv * inv_freq[i];
    float s, c;
    sincosf(fr, &s, &c);
    if (xv == -10.0f) { s = 0.0f; c = 0.0f; }
    h[row*DDIM + i]       = gene_emb[g*DDIM + i]       + s;
    h[row*DDIM + 128 + i] = gene_emb[g*DDIM + 128 + i] + c;
}

// ---------------------------------------------------------------------------
// LayerNorm over D=256: one block (256 threads) per row
// ---------------------------------------------------------------------------
__global__ void ln_kernel(const float* __restrict__ in,
                          const float* __restrict__ gamma,
                          const float* __restrict__ beta,
                          float* __restrict__ out) {
    int row = blockIdx.x;
    int i = threadIdx.x;
    float v = in[row*DDIM + i];
    float s1 = v, s2 = v*v;
    #pragma unroll
    for (int o = 16; o; o >>= 1) {
        s1 += __shfl_xor_sync(0xffffffffu, s1, o);
        s2 += __shfl_xor_sync(0xffffffffu, s2, o);
    }
    __shared__ float r1[8], r2[8];
    if ((i & 31) == 0) { r1[i>>5] = s1; r2[i>>5] = s2; }
    __syncthreads();
    float t1 = 0.f, t2 = 0.f;
    #pragma unroll
    for (int w = 0; w < 8; w++) { t1 += r1[w]; t2 += r2[w]; }
    float m   = t1 * (1.0f/256.0f);
    float var = t2 * (1.0f/256.0f) - m*m;
    float inv = rsqrtf(var + 1e-5f);
    out[row*DDIM + i] = (v - m) * inv * gamma[i] + beta[i];
}

// ---------------------------------------------------------------------------
// Tiled fp32 GEMM: C[M,N] = epi(A[M,K] @ W[K,N] + bias [, resid])
// BM=128, BN=64, BK=16, 256 threads, each thread 8x4 outputs
// EPI: 0 none, 1 square, 2 exact gelu, 3 residual-add
// ---------------------------------------------------------------------------
template<int EPI>
__global__ void gemm_kernel(const float* __restrict__ A,
                            const float* __restrict__ W,
                            const float* __restrict__ bias,
                            const float* __restrict__ resid,
                            float* __restrict__ C,
                            int N, int K) {
    const int BM = 128, BN = 64, BK = 16;
    __shared__ float As[BK][BM];
    __shared__ float Ws[BK][BN];
    int tid = threadIdx.x;
    int bm = blockIdx.x * BM;
    int bn = blockIdx.y * BN;
    int tx = tid & 15;      // 0..15 -> 4 cols each
    int ty = tid >> 4;      // 0..15 -> 8 rows each
    float acc[8][4];
    #pragma unroll
    for (int i = 0; i < 8; i++)
        #pragma unroll
        for (int j = 0; j < 4; j++) acc[i][j] = 0.f;

    int ar  = tid >> 2;          // 0..63
    int ac4 = (tid & 3) * 4;     // 0,4,8,12
    int wr  = tid >> 4;          // 0..15
    int wc  = (tid & 15) * 4;    // 0..60

    for (int k0 = 0; k0 < K; k0 += BK) {
        #pragma unroll
        for (int rr = 0; rr < 2; rr++) {
            float4 a = *(const float4*)&A[(size_t)(bm + ar + rr*64)*K + k0 + ac4];
            As[ac4+0][ar + rr*64] = a.x;
            As[ac4+1][ar + rr*64] = a.y;
            As[ac4+2][ar + rr*64] = a.z;
            As[ac4+3][ar + rr*64] = a.w;
        }
        float4 w4 = *(const float4*)&W[(size_t)(k0 + wr)*N + bn + wc];
        *(float4*)&Ws[wr][wc] = w4;
        __syncthreads();
        #pragma unroll
        for (int kk = 0; kk < BK; kk++) {
            float4 a0 = *(const float4*)&As[kk][ty*8];
            float4 a1 = *(const float4*)&As[kk][ty*8 + 4];
            float4 wv = *(const float4*)&Ws[kk][tx*4];
            float ar_[8] = {a0.x,a0.y,a0.z,a0.w,a1.x,a1.y,a1.z,a1.w};
            float wr_[4] = {wv.x,wv.y,wv.z,wv.w};
            #pragma unroll
            for (int i = 0; i < 8; i++)
                #pragma unroll
                for (int j = 0; j < 4; j++)
                    acc[i][j] = fmaf(ar_[i], wr_[j], acc[i][j]);
        }
        __syncthreads();
    }

    int col0 = bn + tx*4;
    float4 bb = *(const float4*)&bias[col0];
    float bs[4] = {bb.x, bb.y, bb.z, bb.w};
    #pragma unroll
    for (int i = 0; i < 8; i++) {
        size_t row = bm + ty*8 + i;
        float o[4];
        #pragma unroll
        for (int j = 0; j < 4; j++) {
            float vv = acc[i][j] + bs[j];
            if (EPI == 1) vv = vv * vv;
            else if (EPI == 2) vv = 0.5f * vv * (1.0f + erff(vv * 0.70710678118654752f));
            o[j] = vv;
        }
        if (EPI == 3) {
            float4 rs = *(const float4*)&resid[row*N + col0];
            o[0] += rs.x; o[1] += rs.y; o[2] += rs.z; o[3] += rs.w;
        }
        float4 ov = {o[0], o[1], o[2], o[3]};
        *(float4*)&C[row*N + col0] = ov;
    }
}

// ---------------------------------------------------------------------------
// Causal linear attention scan. One block per (batch, head): 1024 threads,
// thread (warp=d, lane=f) holds num_s[f][d]; den_s[f] replicated per warp.
// Writes h += num/(den+1e-16) in place.
// ---------------------------------------------------------------------------
__global__ void attn_kernel(const float* __restrict__ Q,
                            const float* __restrict__ K,
                            const float* __restrict__ V,
                            float* __restrict__ H) {
    int b  = blockIdx.x >> 3;
    int hh = blockIdx.x & 7;
    int tid = threadIdx.x;
    int f = tid & 31;    // lane
    int d = tid >> 5;    // warp
    float num_s = 0.0f;
    float den_s = 0.0f;
    size_t base = ((size_t)b * GDIM) * DDIM + hh * HEADDIM;
    #pragma unroll 2
    for (int t = 0; t < GDIM; t++) {
        float qf = Q[base + f];
        float kf = K[base + f];
        float vd = V[base + d];
        num_s = fmaf(kf, vd, num_s);
        den_s += kf;
        float num = qf * num_s;
        float den = qf * den_s;
        #pragma unroll
        for (int o = 16; o; o >>= 1) {
            num += __shfl_xor_sync(0xffffffffu, num, o);
            den += __shfl_xor_sync(0xffffffffu, den, o);
        }
        if (f == 0) H[base + d] += num / (den + 1e-16f);
        base += DDIM;
    }
}

// ---------------------------------------------------------------------------
// Output projection: out[row] = h[row,:] . Wout + bout  (one warp per row)
// ---------------------------------------------------------------------------
__global__ void outproj_kernel(const float* __restrict__ H,
                               const float* __restrict__ Wout,
                               const float* __restrict__ bout,
                               float* __restrict__ out) {
    int row  = blockIdx.x * 8 + (threadIdx.x >> 5);
    int lane = threadIdx.x & 31;
    float s = 0.f;
    #pragma unroll
    for (int i = 0; i < 8; i++) {
        int c = lane + i*32;
        s += H[(size_t)row*DDIM + c] * Wout[c];
    }
    #pragma unroll
    for (int o = 16; o; o >>= 1) s += __shfl_xor_sync(0xffffffffu, s, o);
    if (lane == 0) out[row] = s + bout[0];
}

// ---------------------------------------------------------------------------
extern "C" void kernel_launch(void* const* d_in, const int* in_sizes, int n_in,
                              void* d_out, int out_size) {
    const float* x        = (const float*)d_in[0];
    const float* gene_emb = (const float*)d_in[1];
    const float* inv_freq = (const float*)d_in[2];
    const float* Wq   = (const float*)d_in[3];
    const float* bq   = (const float*)d_in[4];
    const float* Wk   = (const float*)d_in[5];
    const float* bk   = (const float*)d_in[6];
    const float* Wv   = (const float*)d_in[7];
    const float* bv   = (const float*)d_in[8];
    const float* ln1g = (const float*)d_in[9];
    const float* ln1b = (const float*)d_in[10];
    const float* ln2g = (const float*)d_in[11];
    const float* ln2b = (const float*)d_in[12];
    const float* WU   = (const float*)d_in[13];
    const float* bU   = (const float*)d_in[14];
    const float* WV   = (const float*)d_in[15];
    const float* bV   = (const float*)d_in[16];
    const float* Wout = (const float*)d_in[17];
    const float* bout = (const float*)d_in[18];
    float* out = (float*)d_out;

    float *h, *hn, *q, *k, *v, *mid;
    cudaGetSymbolAddress((void**)&h,   g_h);
    cudaGetSymbolAddress((void**)&hn,  g_hn);
    cudaGetSymbolAddress((void**)&q,   g_q);
    cudaGetSymbolAddress((void**)&k,   g_k);
    cudaGetSymbolAddress((void**)&v,   g_v);
    cudaGetSymbolAddress((void**)&mid, g_mid);

    embed_kernel<<<ROWS, 128>>>(x, gene_emb, inv_freq, h);

    dim3 g256(ROWS/128, DDIM/64);   // N=256
    dim3 g1024(ROWS/128, FFND/64);  // N=1024

    for (int l = 0; l < LAYERS; l++) {
        ln_kernel<<<ROWS, 256>>>(h, ln1g + l*DDIM, ln1b + l*DDIM, hn);
        gemm_kernel<1><<<g256, 256>>>(hn, Wq + (size_t)l*DDIM*DDIM, bq + l*DDIM, nullptr, q, DDIM, DDIM);
        gemm_kernel<1><<<g256, 256>>>(hn, Wk + (size_t)l*DDIM*DDIM, bk + l*DDIM, nullptr, k, DDIM, DDIM);
        gemm_kernel<0><<<g256, 256>>>(hn, Wv + (size_t)l*DDIM*DDIM, bv + l*DDIM, nullptr, v, DDIM, DDIM);
        attn_kernel<<<BDIM*NHEADS, 1024>>>(q, k, v, h);
        ln_kernel<<<ROWS, 256>>>(h, ln2g + l*DDIM, ln2b + l*DDIM, hn);
        gemm_kernel<2><<<g1024, 256>>>(hn, WU + (size_t)l*DDIM*FFND, bU + l*FFND, nullptr, mid, FFND, DDIM);
        gemm_kernel<3><<<g256, 256>>>(mid, WV + (size_t)l*FFND*DDIM, bV + l*DDIM, h, h, DDIM, FFND);
    }

    outproj_kernel<<<ROWS/8, 256>>>(h, Wout, bout, out);
}

// round 8
// speedup vs baseline: 2.3866x; 2.3866x over previous
#include <cuda_runtime.h>
#include <math.h>

#define BDIM 16
#define GDIM 2048
#define DDIM 256
#define NHEADS 8
#define HEADDIM 32
#define FFND 1024
#define LAYERS 4
#define ROWS (BDIM*GDIM)   // 32768
#define CHUNK 64
#define NCHUNK (GDIM/CHUNK)      // 32
#define BH (BDIM*NHEADS)         // 128
#define STATE_STRIDE 1056        // 32*32 + 32

// Scratch (device globals; no runtime allocation allowed)
__device__ float g_h [ROWS*DDIM];
__device__ float g_hn[ROWS*DDIM];
__device__ float g_q [ROWS*DDIM];
__device__ float g_k [ROWS*DDIM];
__device__ float g_v [ROWS*DDIM];
__device__ float g_mid[ROWS*FFND];
__device__ float g_state[(size_t)BH*NCHUNK*STATE_STRIDE];

// ---------------------------------------------------------------------------
// Embedding: h = gene_emb + [sin(x*inv_freq), cos(x*inv_freq)] (0 where masked)
// ---------------------------------------------------------------------------
__global__ void embed_kernel(const float* __restrict__ x,
                             const float* __restrict__ gene_emb,
                             const float* __restrict__ inv_freq,
                             float* __restrict__ h) {
    int row = blockIdx.x;            // 0..ROWS-1
    int g   = row % GDIM;
    int i   = threadIdx.x;           // 0..127
    float xv = x[row];
    float fr = xv * inv_freq[i];
    float s, c;
    sincosf(fr, &s, &c);
    if (xv == -10.0f) { s = 0.0f; c = 0.0f; }
    h[row*DDIM + i]       = gene_emb[g*DDIM + i]       + s;
    h[row*DDIM + 128 + i] = gene_emb[g*DDIM + 128 + i] + c;
}

// ---------------------------------------------------------------------------
// LayerNorm over D=256: one block (256 threads) per row
// ---------------------------------------------------------------------------
__global__ void ln_kernel(const float* __restrict__ in,
                          const float* __restrict__ gamma,
                          const float* __restrict__ beta,
                          float* __restrict__ out) {
    int row = blockIdx.x;
    int i = threadIdx.x;
    float v = in[row*DDIM + i];
    float s1 = v, s2 = v*v;
    #pragma unroll
    for (int o = 16; o; o >>= 1) {
        s1 += __shfl_xor_sync(0xffffffffu, s1, o);
        s2 += __shfl_xor_sync(0xffffffffu, s2, o);
    }
    __shared__ float r1[8], r2[8];
    if ((i & 31) == 0) { r1[i>>5] = s1; r2[i>>5] = s2; }
    __syncthreads();
    float t1 = 0.f, t2 = 0.f;
    #pragma unroll
    for (int w = 0; w < 8; w++) { t1 += r1[w]; t2 += r2[w]; }
    float m   = t1 * (1.0f/256.0f);
    float var = t2 * (1.0f/256.0f) - m*m;
    float inv = rsqrtf(var + 1e-5f);
    out[row*DDIM + i] = (v - m) * inv * gamma[i] + beta[i];
}

// ---------------------------------------------------------------------------
// Tiled fp32 GEMM: C[M,N] = epi(A[M,K] @ W[K,N] + bias [, resid])
// BM=128, BN=64, BK=16, 256 threads, each thread 8x4 outputs
// EPI: 0 none, 1 square, 2 exact gelu, 3 residual-add
// ---------------------------------------------------------------------------
template<int EPI>
__global__ void gemm_kernel(const float* __restrict__ A,
                            const float* __restrict__ W,
                            const float* __restrict__ bias,
                            const float* __restrict__ resid,
                            float* __restrict__ C,
                            int N, int K) {
    const int BM = 128, BN = 64, BK = 16;
    __shared__ float As[BK][BM];
    __shared__ float Ws[BK][BN];
    int tid = threadIdx.x;
    int bm = blockIdx.x * BM;
    int bn = blockIdx.y * BN;
    int tx = tid & 15;      // 0..15 -> 4 cols each
    int ty = tid >> 4;      // 0..15 -> 8 rows each
    float acc[8][4];
    #pragma unroll
    for (int i = 0; i < 8; i++)
        #pragma unroll
        for (int j = 0; j < 4; j++) acc[i][j] = 0.f;

    int ar  = tid >> 2;          // 0..63
    int ac4 = (tid & 3) * 4;     // 0,4,8,12
    int wr  = tid >> 4;          // 0..15
    int wc  = (tid & 15) * 4;    // 0..60

    for (int k0 = 0; k0 < K; k0 += BK) {
        #pragma unroll
        for (int rr = 0; rr < 2; rr++) {
            float4 a = *(const float4*)&A[(size_t)(bm + ar + rr*64)*K + k0 + ac4];
            As[ac4+0][ar + rr*64] = a.x;
            As[ac4+1][ar + rr*64] = a.y;
            As[ac4+2][ar + rr*64] = a.z;
            As[ac4+3][ar + rr*64] = a.w;
        }
        float4 w4 = *(const float4*)&W[(size_t)(k0 + wr)*N + bn + wc];
        *(float4*)&Ws[wr][wc] = w4;
        __syncthreads();
        #pragma unroll
        for (int kk = 0; kk < BK; kk++) {
            float4 a0 = *(const float4*)&As[kk][ty*8];
            float4 a1 = *(const float4*)&As[kk][ty*8 + 4];
            float4 wv = *(const float4*)&Ws[kk][tx*4];
            float ar_[8] = {a0.x,a0.y,a0.z,a0.w,a1.x,a1.y,a1.z,a1.w};
            float wr_[4] = {wv.x,wv.y,wv.z,wv.w};
            #pragma unroll
            for (int i = 0; i < 8; i++)
                #pragma unroll
                for (int j = 0; j < 4; j++)
                    acc[i][j] = fmaf(ar_[i], wr_[j], acc[i][j]);
        }
        __syncthreads();
    }

    int col0 = bn + tx*4;
    float4 bb = *(const float4*)&bias[col0];
    float bs[4] = {bb.x, bb.y, bb.z, bb.w};
    #pragma unroll
    for (int i = 0; i < 8; i++) {
        size_t row = bm + ty*8 + i;
        float o[4];
        #pragma unroll
        for (int j = 0; j < 4; j++) {
            float vv = acc[i][j] + bs[j];
            if (EPI == 1) vv = vv * vv;
            else if (EPI == 2) vv = 0.5f * vv * (1.0f + erff(vv * 0.70710678118654752f));
            o[j] = vv;
        }
        if (EPI == 3) {
            float4 rs = *(const float4*)&resid[row*N + col0];
            o[0] += rs.x; o[1] += rs.y; o[2] += rs.z; o[3] += rs.w;
        }
        float4 ov = {o[0], o[1], o[2], o[3]};
        *(float4*)&C[row*N + col0] = ov;
    }
}

// ---------------------------------------------------------------------------
// Chunked causal linear attention.
// Stage A: per-(bh,chunk) state: S[f][d] = sum_t k[t][f]*v[t][d], ksum[f].
// Stage B: exclusive prefix over chunks per (bh).
// Stage C: per-(bh,chunk) output: out = (Q@Sprev + tril(QK^T)@V) / den.
// ---------------------------------------------------------------------------
__global__ void attn_state_kernel(const float* __restrict__ K,
                                  const float* __restrict__ V,
                                  float* __restrict__ state) {
    int blk = blockIdx.x;            // bh*NCHUNK + c
    int bh  = blk >> 5;              // NCHUNK=32
    int c   = blk & 31;
    int b = bh >> 3, hh = bh & 7;
    int f = threadIdx.x & 31;
    int d = threadIdx.x >> 5;
    size_t base = ((size_t)(b*GDIM + c*CHUNK))*DDIM + hh*HEADDIM;
    float s = 0.f, ks = 0.f;
    #pragma unroll 4
    for (int t = 0; t < CHUNK; t++) {
        float kf = K[base + f];
        float vd = V[base + d];
        s  = fmaf(kf, vd, s);
        ks += kf;
        base += DDIM;
    }
    float* st = state + (size_t)blk * STATE_STRIDE;
    st[d*32 + f] = s;
    if (d == 0) st[1024 + f] = ks;
}

__global__ void attn_prefix_kernel(float* __restrict__ state) {
    int bh = blockIdx.x;
    float* st = state + (size_t)bh * NCHUNK * STATE_STRIDE;
    for (int e = threadIdx.x; e < STATE_STRIDE; e += blockDim.x) {
        float run = 0.f;
        float* p = st + e;
        #pragma unroll 4
        for (int c = 0; c < NCHUNK; c++) {
            float t = *p;
            *p = run;      // exclusive prefix
            run += t;
            p += STATE_STRIDE;
        }
    }
}

__global__ __launch_bounds__(256) void attn_out_kernel(
        const float* __restrict__ Q,
        const float* __restrict__ K,
        const float* __restrict__ V,
        const float* __restrict__ state,
        float* __restrict__ H) {
    int blk = blockIdx.x;
    int bh  = blk >> 5;
    int c   = blk & 31;
    int b = bh >> 3, hh = bh & 7;

    __shared__ float Qs[CHUNK*33];
    __shared__ float Ks[CHUNK*33];
    __shared__ float Vs[CHUNK*33];
    __shared__ float Sp[32*33];
    __shared__ float kp[32];
    __shared__ float Am[CHUNK*65];
    __shared__ float den[CHUNK];

    int tid  = threadIdx.x;
    int lane = tid & 31;
    int w    = tid >> 5;     // 8 warps
    size_t rowbase = ((size_t)(b*GDIM + c*CHUNK))*DDIM + hh*HEADDIM;

    for (int t = w; t < CHUNK; t += 8) {
        size_t g = rowbase + (size_t)t*DDIM + lane;
        Qs[t*33 + lane] = Q[g];
        Ks[t*33 + lane] = K[g];
        Vs[t*33 + lane] = V[g];
    }
    const float* st = state + (size_t)blk * STATE_STRIDE;
    for (int e = tid; e < 1024; e += 256)
        Sp[(e & 31)*33 + (e >> 5)] = st[e];   // Sp[f][d]
    if (tid < 32) kp[tid] = st[1024 + tid];
    __syncthreads();

    // A = tril(Q K^T): each thread a 4x4 tile
    {
        int tt = (tid >> 4) << 2;
        int ss = (tid & 15) << 2;
        float acc[4][4];
        #pragma unroll
        for (int i = 0; i < 4; i++)
            #pragma unroll
            for (int j = 0; j < 4; j++) acc[i][j] = 0.f;
        for (int f = 0; f < 32; f++) {
            float qv[4], kv[4];
            #pragma unroll
            for (int i = 0; i < 4; i++) qv[i] = Qs[(tt+i)*33 + f];
            #pragma unroll
            for (int j = 0; j < 4; j++) kv[j] = Ks[(ss+j)*33 + f];
            #pragma unroll
            for (int i = 0; i < 4; i++)
                #pragma unroll
                for (int j = 0; j < 4; j++)
                    acc[i][j] = fmaf(qv[i], kv[j], acc[i][j]);
        }
        #pragma unroll
        for (int i = 0; i < 4; i++)
            #pragma unroll
            for (int j = 0; j < 4; j++)
                Am[(tt+i)*65 + ss+j] = (ss+j <= tt+i) ? acc[i][j] : 0.f;
    }
    __syncthreads();

    // den[t] = q_t . kprev + rowsum(A[t])
    if (tid < CHUNK) {
        float s = 0.f;
        for (int ss = 0; ss <= tid; ss++) s += Am[tid*65 + ss];
        for (int f = 0; f < 32; f++) s += Qs[tid*33 + f] * kp[f];
        den[tid] = s + 1e-16f;
    }
    __syncthreads();

    // out[t][d] = sum_f Qs[t][f]*Sp[f][d] + sum_s A[t][s]*Vs[s][d]
    int d = lane;
    float acc[8];
    #pragma unroll
    for (int i = 0; i < 8; i++) acc[i] = 0.f;
    for (int f = 0; f < 32; f++) {
        float sp = Sp[f*33 + d];
        #pragma unroll
        for (int i = 0; i < 8; i++)
            acc[i] = fmaf(Qs[(w*8+i)*33 + f], sp, acc[i]);
    }
    for (int s = 0; s < CHUNK; s++) {
        float vv = Vs[s*33 + d];
        #pragma unroll
        for (int i = 0; i < 8; i++)
            acc[i] = fmaf(Am[(w*8+i)*65 + s], vv, acc[i]);
    }
    #pragma unroll
    for (int i = 0; i < 8; i++) {
        int t = w*8 + i;
        H[rowbase + (size_t)t*DDIM + d] += acc[i] / den[t];
    }
}

// ---------------------------------------------------------------------------
// Output projection: out[row] = h[row,:] . Wout + bout  (one warp per row)
// ---------------------------------------------------------------------------
__global__ void outproj_kernel(const float* __restrict__ H,
                               const float* __restrict__ Wout,
                               const float* __restrict__ bout,
                               float* __restrict__ out) {
    int row  = blockIdx.x * 8 + (threadIdx.x >> 5);
    int lane = threadIdx.x & 31;
    float s = 0.f;
    #pragma unroll
    for (int i = 0; i < 8; i++) {
        int c = lane + i*32;
        s += H[(size_t)row*DDIM + c] * Wout[c];
    }
    #pragma unroll
    for (int o = 16; o; o >>= 1) s += __shfl_xor_sync(0xffffffffu, s, o);
    if (lane == 0) out[row] = s + bout[0];
}

// ---------------------------------------------------------------------------
extern "C" void kernel_launch(void* const* d_in, const int* in_sizes, int n_in,
                              void* d_out, int out_size) {
    const float* x        = (const float*)d_in[0];
    const float* gene_emb = (const float*)d_in[1];
    const float* inv_freq = (const float*)d_in[2];
    const float* Wq   = (const float*)d_in[3];
    const float* bq   = (const float*)d_in[4];
    const float* Wk   = (const float*)d_in[5];
    const float* bk   = (const float*)d_in[6];
    const float* Wv   = (const float*)d_in[7];
    const float* bv   = (const float*)d_in[8];
    const float* ln1g = (const float*)d_in[9];
    const float* ln1b = (const float*)d_in[10];
    const float* ln2g = (const float*)d_in[11];
    const float* ln2b = (const float*)d_in[12];
    const float* WU   = (const float*)d_in[13];
    const float* bU   = (const float*)d_in[14];
    const float* WV   = (const float*)d_in[15];
    const float* bV   = (const float*)d_in[16];
    const float* Wout = (const float*)d_in[17];
    const float* bout = (const float*)d_in[18];
    float* out = (float*)d_out;

    float *h, *hn, *q, *k, *v, *mid, *stt;
    cudaGetSymbolAddress((void**)&h,   g_h);
    cudaGetSymbolAddress((void**)&hn,  g_hn);
    cudaGetSymbolAddress((void**)&q,   g_q);
    cudaGetSymbolAddress((void**)&k,   g_k);
    cudaGetSymbolAddress((void**)&v,   g_v);
    cudaGetSymbolAddress((void**)&mid, g_mid);
    cudaGetSymbolAddress((void**)&stt, g_state);

    embed_kernel<<<ROWS, 128>>>(x, gene_emb, inv_freq, h);

    dim3 g256(ROWS/128, DDIM/64);   // N=256
    dim3 g1024(ROWS/128, FFND/64);  // N=1024

    for (int l = 0; l < LAYERS; l++) {
        ln_kernel<<<ROWS, 256>>>(h, ln1g + l*DDIM, ln1b + l*DDIM, hn);
        gemm_kernel<1><<<g256, 256>>>(hn, Wq + (size_t)l*DDIM*DDIM, bq + l*DDIM, nullptr, q, DDIM, DDIM);
        gemm_kernel<1><<<g256, 256>>>(hn, Wk + (size_t)l*DDIM*DDIM, bk + l*DDIM, nullptr, k, DDIM, DDIM);
        gemm_kernel<0><<<g256, 256>>>(hn, Wv + (size_t)l*DDIM*DDIM, bv + l*DDIM, nullptr, v, DDIM, DDIM);

        attn_state_kernel <<<BH*NCHUNK, 1024>>>(k, v, stt);
        attn_prefix_kernel<<<BH, 1024>>>(stt);
        attn_out_kernel   <<<BH*NCHUNK, 256>>>(q, k, v, stt, h);

        ln_kernel<<<ROWS, 256>>>(h, ln2g + l*DDIM, ln2b + l*DDIM, hn);
        gemm_kernel<2><<<g1024, 256>>>(hn, WU + (size_t)l*DDIM*FFND, bU + l*FFND, nullptr, mid, FFND, DDIM);
        gemm_kernel<3><<<g256, 256>>>(mid, WV + (size_t)l*FFND*DDIM, bV + l*DDIM, h, h, DDIM, FFND);
    }

    outproj_kernel<<<ROWS/8, 256>>>(h, Wout, bout, out);
}

// round 11
// speedup vs baseline: 3.8853x; 1.6279x over previous
#include <cuda_runtime.h>
#include <cuda_bf16.h>
#include <cstdint>
#include <math.h>

#define BDIM 16
#define GDIM 2048
#define DDIM 256
#define NHEADS 8
#define HEADDIM 32
#define FFND 1024
#define LAYERS 4
#define ROWS (BDIM*GDIM)   // 32768
#define CHUNK 64
#define NCHUNK (GDIM/CHUNK)      // 32
#define BH (BDIM*NHEADS)         // 128
#define STATE_STRIDE 1056        // 32*32 + 32

// ---------------------------------------------------------------------------
// Scratch (device globals; no runtime allocation allowed)
// ---------------------------------------------------------------------------
__device__ float g_h [ROWS*DDIM];
__device__ float g_q [ROWS*DDIM];
__device__ float g_k [ROWS*DDIM];
__device__ float g_v [ROWS*DDIM];
__device__ float g_state[(size_t)BH*NCHUNK*STATE_STRIDE];

__device__ __nv_bfloat16 g_hnhi[ROWS*DDIM],  g_hnlo[ROWS*DDIM];
__device__ __nv_bfloat16 g_midhi[(size_t)ROWS*FFND], g_midlo[(size_t)ROWS*FFND];
// Transposed split weights: [N, K] layout per matrix
__device__ __nv_bfloat16 g_wqh[LAYERS*DDIM*DDIM], g_wql[LAYERS*DDIM*DDIM];
__device__ __nv_bfloat16 g_wkh[LAYERS*DDIM*DDIM], g_wkl[LAYERS*DDIM*DDIM];
__device__ __nv_bfloat16 g_wvh[LAYERS*DDIM*DDIM], g_wvl[LAYERS*DDIM*DDIM];
__device__ __nv_bfloat16 g_wuh[LAYERS*DDIM*FFND], g_wul[LAYERS*DDIM*FFND];
__device__ __nv_bfloat16 g_wvh2[LAYERS*FFND*DDIM], g_wvl2[LAYERS*FFND*DDIM];

// ---------------------------------------------------------------------------
// Warp-level MMA helpers (base sm_103-legal PTX: ldmatrix + mma.sync bf16)
// ---------------------------------------------------------------------------
__device__ __forceinline__ uint32_t smem_to_u32(const void* p) {
    uint32_t a;
    asm("{ .reg .u64 t; cvta.to.shared.u64 t, %1; cvt.u32.u64 %0, t; }" : "=r"(a) : "l"(p));
    return a;
}
__device__ __forceinline__ void ldsm4(uint32_t* r, uint32_t addr) {
    asm volatile("ldmatrix.sync.aligned.m8n8.x4.shared.b16 {%0,%1,%2,%3}, [%4];"
        : "=r"(r[0]), "=r"(r[1]), "=r"(r[2]), "=r"(r[3]) : "r"(addr));
}
__device__ __forceinline__ void ldsm2(uint32_t* r, uint32_t addr) {
    asm volatile("ldmatrix.sync.aligned.m8n8.x2.shared.b16 {%0,%1}, [%2];"
        : "=r"(r[0]), "=r"(r[1]) : "r"(addr));
}
__device__ __forceinline__ void mma16816(float* c, const uint32_t* a, const uint32_t* b) {
    asm volatile(
        "mma.sync.aligned.m16n8k16.row.col.f32.bf16.bf16.f32 "
        "{%0,%1,%2,%3}, {%4,%5,%6,%7}, {%8,%9}, {%0,%1,%2,%3};"
        : "+f"(c[0]), "+f"(c[1]), "+f"(c[2]), "+f"(c[3])
        : "r"(a[0]), "r"(a[1]), "r"(a[2]), "r"(a[3]), "r"(b[0]), "r"(b[1]));
}

// ---------------------------------------------------------------------------
// Embedding
// ---------------------------------------------------------------------------
__global__ void embed_kernel(const float* __restrict__ x,
                             const float* __restrict__ gene_emb,
                             const float* __restrict__ inv_freq,
                             float* __restrict__ h) {
    int row = blockIdx.x;
    int g   = row % GDIM;
    int i   = threadIdx.x;
    float xv = x[row];
    float fr = xv * inv_freq[i];
    float s, c;
    sincosf(fr, &s, &c);
    if (xv == -10.0f) { s = 0.0f; c = 0.0f; }
    h[row*DDIM + i]       = gene_emb[g*DDIM + i]       + s;
    h[row*DDIM + 128 + i] = gene_emb[g*DDIM + 128 + i] + c;
}

// ---------------------------------------------------------------------------
// LayerNorm -> split bf16 (hi/lo) output
// ---------------------------------------------------------------------------
__global__ void ln_bf16_kernel(const float* __restrict__ in,
                               const float* __restrict__ gamma,
                               const float* __restrict__ beta,
                               __nv_bfloat16* __restrict__ ohi,
                               __nv_bfloat16* __restrict__ olo) {
    int row = blockIdx.x;
    int i = threadIdx.x;
    float v = in[row*DDIM + i];
    float s1 = v, s2 = v*v;
    #pragma unroll
    for (int o = 16; o; o >>= 1) {
        s1 += __shfl_xor_sync(0xffffffffu, s1, o);
        s2 += __shfl_xor_sync(0xffffffffu, s2, o);
    }
    __shared__ float r1[8], r2[8];
    if ((i & 31) == 0) { r1[i>>5] = s1; r2[i>>5] = s2; }
    __syncthreads();
    float t1 = 0.f, t2 = 0.f;
    #pragma unroll
    for (int w = 0; w < 8; w++) { t1 += r1[w]; t2 += r2[w]; }
    float m   = t1 * (1.0f/256.0f);
    float var = t2 * (1.0f/256.0f) - m*m;
    float inv = rsqrtf(var + 1e-5f);
    float y = (v - m) * inv * gamma[i] + beta[i];
    __nv_bfloat16 hi = __float2bfloat16(y);
    __nv_bfloat16 lo = __float2bfloat16(y - __bfloat162float(hi));
    ohi[(size_t)row*DDIM + i] = hi;
    olo[(size_t)row*DDIM + i] = lo;
}

// ---------------------------------------------------------------------------
// Weight transpose + split: W[K,N] fp32 -> out[N,K] bf16 hi/lo
// ---------------------------------------------------------------------------
__global__ void wconv_kernel(const float* __restrict__ W,
                             __nv_bfloat16* __restrict__ hi,
                             __nv_bfloat16* __restrict__ lo,
                             int K, int N) {
    __shared__ float t[32][33];
    int nb = blockIdx.x*32, kb = blockIdx.y*32;
    int tx = threadIdx.x & 31, ty = threadIdx.x >> 5;
    #pragma unroll
    for (int j = 0; j < 32; j += 8)
        t[ty+j][tx] = W[(size_t)(kb+ty+j)*N + nb+tx];
    __syncthreads();
    #pragma unroll
    for (int j = 0; j < 32; j += 8) {
        float v = t[tx][ty+j];
        __nv_bfloat16 h = __float2bfloat16(v);
        __nv_bfloat16 l = __float2bfloat16(v - __bfloat162float(h));
        size_t o = (size_t)(nb+ty+j)*K + kb+tx;
        hi[o] = h; lo[o] = l;
    }
}

// ---------------------------------------------------------------------------
// Warp-MMA split-bf16 GEMM: C[M,N] = epi(A @ W + bias [, resid])
// A hi/lo bf16 [M,K] row-major; B (=W^T) hi/lo bf16 [N,K] row-major.
// BM=128, BN=64, BK=64; 8 warps (2 in M x 4 in N), warp tile 64x16.
// EPI: 0 none(fp32), 1 square(fp32), 2 gelu->bf16 hi/lo, 3 resid add(fp32)
// ---------------------------------------------------------------------------
#define AS_STRIDE 72
#define OFF_AHI 0
#define OFF_ALO (128*AS_STRIDE*2)              // 18432
#define OFF_BHI (2*128*AS_STRIDE*2)            // 36864
#define OFF_BLO (2*128*AS_STRIDE*2 + 64*AS_STRIDE*2)  // 46080
#define SM_TOTAL (2*128*AS_STRIDE*2 + 2*64*AS_STRIDE*2) // 55296

template<int EPI>
__global__ __launch_bounds__(256, 2) void tc_gemm(
    const __nv_bfloat16* __restrict__ Ahi, const __nv_bfloat16* __restrict__ Alo,
    const __nv_bfloat16* __restrict__ Bhi, const __nv_bfloat16* __restrict__ Blo,
    const float* __restrict__ bias, const float* __restrict__ resid,
    float* __restrict__ Cf,
    __nv_bfloat16* __restrict__ Chi, __nv_bfloat16* __restrict__ Clo,
    int N, int K)
{
    extern __shared__ char smem[];
    __nv_bfloat16* As_hi = (__nv_bfloat16*)(smem + OFF_AHI);
    __nv_bfloat16* As_lo = (__nv_bfloat16*)(smem + OFF_ALO);
    __nv_bfloat16* Bs_hi = (__nv_bfloat16*)(smem + OFF_BHI);
    __nv_bfloat16* Bs_lo = (__nv_bfloat16*)(smem + OFF_BLO);
    uint32_t sbase = smem_to_u32(smem);

    int tid  = threadIdx.x;
    int lane = tid & 31;
    int warp = tid >> 5;
    int wm = warp >> 2;   // 0..1
    int wn = warp & 3;    // 0..3
    int bm = blockIdx.x * 128, bn = blockIdx.y * 64;

    float acc[4][2][4];
    #pragma unroll
    for (int mi = 0; mi < 4; mi++)
        #pragma unroll
        for (int ni = 0; ni < 2; ni++)
            #pragma unroll
            for (int e = 0; e < 4; e++) acc[mi][ni][e] = 0.f;

    for (int kt = 0; kt < K; kt += 64) {
        // ---- load A tile (128 x 64) hi/lo
        #pragma unroll
        for (int i = tid; i < 1024; i += 256) {
            int r = i >> 3, kc = (i & 7) * 8;
            size_t go = (size_t)(bm + r) * K + kt + kc;
            *(uint4*)&As_hi[r*AS_STRIDE + kc] = *(const uint4*)&Ahi[go];
            *(uint4*)&As_lo[r*AS_STRIDE + kc] = *(const uint4*)&Alo[go];
        }
        // ---- load B tile (64 x 64) hi/lo
        #pragma unroll
        for (int i = tid; i < 512; i += 256) {
            int r = i >> 3, kc = (i & 7) * 8;
            size_t go = (size_t)(bn + r) * K + kt + kc;
            *(uint4*)&Bs_hi[r*AS_STRIDE + kc] = *(const uint4*)&Bhi[go];
            *(uint4*)&Bs_lo[r*AS_STRIDE + kc] = *(const uint4*)&Blo[go];
        }
        __syncthreads();

        int ar = lane & 15, ac = (lane >> 4) * 8;
        int br = lane & 7,  bc = ((lane >> 3) & 1) * 8;
        #pragma unroll
        for (int ks = 0; ks < 4; ks++) {
            uint32_t ah[4][4], al[4][4], bh[2][2], bl[2][2];
            #pragma unroll
            for (int mi = 0; mi < 4; mi++) {
                uint32_t ad = sbase + (uint32_t)(((wm*64 + mi*16 + ar)*AS_STRIDE + ks*16 + ac) * 2);
                ldsm4(ah[mi], ad + OFF_AHI);
                ldsm4(al[mi], ad + OFF_ALO);
            }
            #pragma unroll
            for (int ni = 0; ni < 2; ni++) {
                uint32_t bd = sbase + (uint32_t)(((wn*16 + ni*8 + br)*AS_STRIDE + ks*16 + bc) * 2);
                ldsm2(bh[ni], bd + OFF_BHI);
                ldsm2(bl[ni], bd + OFF_BLO);
            }
            #pragma unroll
            for (int mi = 0; mi < 4; mi++)
                #pragma unroll
                for (int ni = 0; ni < 2; ni++) {
                    mma16816(acc[mi][ni], ah[mi], bh[ni]);
                    mma16816(acc[mi][ni], ah[mi], bl[ni]);
                    mma16816(acc[mi][ni], al[mi], bh[ni]);
                }
        }
        __syncthreads();
    }

    // ---- epilogue: direct register -> gmem
    int r0 = lane >> 2, c0 = (lane & 3) * 2;
    #pragma unroll
    for (int mi = 0; mi < 4; mi++) {
        #pragma unroll
        for (int ni = 0; ni < 2; ni++) {
            int col = bn + wn*16 + ni*8 + c0;
            float b0 = __ldg(&bias[col]), b1 = __ldg(&bias[col+1]);
            #pragma unroll
            for (int hrow = 0; hrow < 2; hrow++) {
                int row = bm + wm*64 + mi*16 + r0 + hrow*8;
                float v0 = acc[mi][ni][hrow*2+0] + b0;
                float v1 = acc[mi][ni][hrow*2+1] + b1;
                size_t o = (size_t)row * N + col;
                if (EPI == 1) {
                    float2 ov = {v0*v0, v1*v1};
                    *(float2*)&Cf[o] = ov;
                } else if (EPI == 2) {
                    float gg0 = 0.5f * v0 * (1.0f + erff(v0 * 0.70710678118654752f));
                    float gg1 = 0.5f * v1 * (1.0f + erff(v1 * 0.70710678118654752f));
                    __nv_bfloat16 h0 = __float2bfloat16(gg0);
                    __nv_bfloat16 h1 = __float2bfloat16(gg1);
                    __nv_bfloat162 hv; hv.x = h0; hv.y = h1;
                    __nv_bfloat162 lv;
                    lv.x = __float2bfloat16(gg0 - __bfloat162float(h0));
                    lv.y = __float2bfloat16(gg1 - __bfloat162float(h1));
                    *(__nv_bfloat162*)&Chi[o] = hv;
                    *(__nv_bfloat162*)&Clo[o] = lv;
                } else if (EPI == 3) {
                    float2 rs = *(const float2*)&resid[o];
                    float2 ov = {v0 + rs.x, v1 + rs.y};
                    *(float2*)&Cf[o] = ov;
                } else {
                    float2 ov = {v0, v1};
                    *(float2*)&Cf[o] = ov;
                }
            }
        }
    }
}

// ---------------------------------------------------------------------------
// Chunked causal linear attention (unchanged from R4 win)
// ---------------------------------------------------------------------------
__global__ void attn_state_kernel(const float* __restrict__ K,
                                  const float* __restrict__ V,
                                  float* __restrict__ state) {
    int blk = blockIdx.x;
    int bh  = blk >> 5;
    int c   = blk & 31;
    int b = bh >> 3, hh = bh & 7;
    int f = threadIdx.x & 31;
    int d = threadIdx.x >> 5;
    size_t base = ((size_t)(b*GDIM + c*CHUNK))*DDIM + hh*HEADDIM;
    float s = 0.f, ks = 0.f;
    #pragma unroll 4
    for (int t = 0; t < CHUNK; t++) {
        float kf = K[base + f];
        float vd = V[base + d];
        s  = fmaf(kf, vd, s);
        ks += kf;
        base += DDIM;
    }
    float* st = state + (size_t)blk * STATE_STRIDE;
    st[d*32 + f] = s;
    if (d == 0) st[1024 + f] = ks;
}

__global__ void attn_prefix_kernel(float* __restrict__ state) {
    int bh = blockIdx.x;
    float* st = state + (size_t)bh * NCHUNK * STATE_STRIDE;
    for (int e = threadIdx.x; e < STATE_STRIDE; e += blockDim.x) {
        float run = 0.f;
        float* p = st + e;
        #pragma unroll 4
        for (int c = 0; c < NCHUNK; c++) {
            float t = *p;
            *p = run;
            run += t;
            p += STATE_STRIDE;
        }
    }
}

__global__ __launch_bounds__(256) void attn_out_kernel(
        const float* __restrict__ Q,
        const float* __restrict__ K,
        const float* __restrict__ V,
        const float* __restrict__ state,
        float* __restrict__ H) {
    int blk = blockIdx.x;
    int bh  = blk >> 5;
    int c   = blk & 31;
    int b = bh >> 3, hh = bh & 7;

    __shared__ float Qs[CHUNK*33];
    __shared__ float Ks[CHUNK*33];
    __shared__ float Vs[CHUNK*33];
    __shared__ float Sp[32*33];
    __shared__ float kp[32];
    __shared__ float Am[CHUNK*65];
    __shared__ float den[CHUNK];

    int tid  = threadIdx.x;
    int lane = tid & 31;
    int w    = tid >> 5;
    size_t rowbase = ((size_t)(b*GDIM + c*CHUNK))*DDIM + hh*HEADDIM;

    for (int t = w; t < CHUNK; t += 8) {
        size_t g = rowbase + (size_t)t*DDIM + lane;
        Qs[t*33 + lane] = Q[g];
        Ks[t*33 + lane] = K[g];
        Vs[t*33 + lane] = V[g];
    }
    const float* st = state + (size_t)blk * STATE_STRIDE;
    for (int e = tid; e < 1024; e += 256)
        Sp[(e & 31)*33 + (e >> 5)] = st[e];
    if (tid < 32) kp[tid] = st[1024 + tid];
    __syncthreads();

    {
        int tt = (tid >> 4) << 2;
        int ss = (tid & 15) << 2;
        float acc[4][4];
        #pragma unroll
        for (int i = 0; i < 4; i++)
            #pragma unroll
            for (int j = 0; j < 4; j++) acc[i][j] = 0.f;
        for (int f = 0; f < 32; f++) {
            float qv[4], kv[4];
            #pragma unroll
            for (int i = 0; i < 4; i++) qv[i] = Qs[(tt+i)*33 + f];
            #pragma unroll
            for (int j = 0; j < 4; j++) kv[j] = Ks[(ss+j)*33 + f];
            #pragma unroll
            for (int i = 0; i < 4; i++)
                #pragma unroll
                for (int j = 0; j < 4; j++)
                    acc[i][j] = fmaf(qv[i], kv[j], acc[i][j]);
        }
        #pragma unroll
        for (int i = 0; i < 4; i++)
            #pragma unroll
            for (int j = 0; j < 4; j++)
                Am[(tt+i)*65 + ss+j] = (ss+j <= tt+i) ? acc[i][j] : 0.f;
    }
    __syncthreads();

    if (tid < CHUNK) {
        float s = 0.f;
        for (int ss = 0; ss <= tid; ss++) s += Am[tid*65 + ss];
        for (int f = 0; f < 32; f++) s += Qs[tid*33 + f] * kp[f];
        den[tid] = s + 1e-16f;
    }
    __syncthreads();

    int d = lane;
    float acc[8];
    #pragma unroll
    for (int i = 0; i < 8; i++) acc[i] = 0.f;
    for (int f = 0; f < 32; f++) {
        float sp = Sp[f*33 + d];
        #pragma unroll
        for (int i = 0; i < 8; i++)
            acc[i] = fmaf(Qs[(w*8+i)*33 + f], sp, acc[i]);
    }
    for (int s = 0; s < CHUNK; s++) {
        float vv = Vs[s*33 + d];
        #pragma unroll
        for (int i = 0; i < 8; i++)
            acc[i] = fmaf(Am[(w*8+i)*65 + s], vv, acc[i]);
    }
    #pragma unroll
    for (int i = 0; i < 8; i++) {
        int t = w*8 + i;
        H[rowbase + (size_t)t*DDIM + d] += acc[i] / den[t];
    }
}

// ---------------------------------------------------------------------------
// Output projection
// ---------------------------------------------------------------------------
__global__ void outproj_kernel(const float* __restrict__ H,
                               const float* __restrict__ Wout,
                               const float* __restrict__ bout,
                               float* __restrict__ out) {
    int row  = blockIdx.x * 8 + (threadIdx.x >> 5);
    int lane = threadIdx.x & 31;
    float s = 0.f;
    #pragma unroll
    for (int i = 0; i < 8; i++) {
        int c = lane + i*32;
        s += H[(size_t)row*DDIM + c] * Wout[c];
    }
    #pragma unroll
    for (int o = 16; o; o >>= 1) s += __shfl_xor_sync(0xffffffffu, s, o);
    if (lane == 0) out[row] = s + bout[0];
}

// ---------------------------------------------------------------------------
extern "C" void kernel_launch(void* const* d_in, const int* in_sizes, int n_in,
                              void* d_out, int out_size) {
    const float* x        = (const float*)d_in[0];
    const float* gene_emb = (const float*)d_in[1];
    const float* inv_freq = (const float*)d_in[2];
    const float* Wq   = (const float*)d_in[3];
    const float* bq   = (const float*)d_in[4];
    const float* Wk   = (const float*)d_in[5];
    const float* bk   = (const float*)d_in[6];
    const float* Wv   = (const float*)d_in[7];
    const float* bv   = (const float*)d_in[8];
    const float* ln1g = (const float*)d_in[9];
    const float* ln1b = (const float*)d_in[10];
    const float* ln2g = (const float*)d_in[11];
    const float* ln2b = (const float*)d_in[12];
    const float* WU   = (const float*)d_in[13];
    const float* bU   = (const float*)d_in[14];
    const float* WV   = (const float*)d_in[15];
    const float* bV   = (const float*)d_in[16];
    const float* Wout = (const float*)d_in[17];
    const float* bout = (const float*)d_in[18];
    float* out = (float*)d_out;

    float *h, *q, *k, *v, *stt;
    cudaGetSymbolAddress((void**)&h,   g_h);
    cudaGetSymbolAddress((void**)&q,   g_q);
    cudaGetSymbolAddress((void**)&k,   g_k);
    cudaGetSymbolAddress((void**)&v,   g_v);
    cudaGetSymbolAddress((void**)&stt, g_state);

    __nv_bfloat16 *hnhi, *hnlo, *midhi, *midlo;
    __nv_bfloat16 *wqh, *wql, *wkh, *wkl, *wvh, *wvl, *wuh, *wul, *wvh2, *wvl2;
    cudaGetSymbolAddress((void**)&hnhi,  g_hnhi);
    cudaGetSymbolAddress((void**)&hnlo,  g_hnlo);
    cudaGetSymbolAddress((void**)&midhi, g_midhi);
    cudaGetSymbolAddress((void**)&midlo, g_midlo);
    cudaGetSymbolAddress((void**)&wqh,  g_wqh);
    cudaGetSymbolAddress((void**)&wql,  g_wql);
    cudaGetSymbolAddress((void**)&wkh,  g_wkh);
    cudaGetSymbolAddress((void**)&wkl,  g_wkl);
    cudaGetSymbolAddress((void**)&wvh,  g_wvh);
    cudaGetSymbolAddress((void**)&wvl,  g_wvl);
    cudaGetSymbolAddress((void**)&wuh,  g_wuh);
    cudaGetSymbolAddress((void**)&wul,  g_wul);
    cudaGetSymbolAddress((void**)&wvh2, g_wvh2);
    cudaGetSymbolAddress((void**)&wvl2, g_wvl2);

    cudaFuncSetAttribute(tc_gemm<0>, cudaFuncAttributeMaxDynamicSharedMemorySize, SM_TOTAL);
    cudaFuncSetAttribute(tc_gemm<1>, cudaFuncAttributeMaxDynamicSharedMemorySize, SM_TOTAL);
    cudaFuncSetAttribute(tc_gemm<2>, cudaFuncAttributeMaxDynamicSharedMemorySize, SM_TOTAL);
    cudaFuncSetAttribute(tc_gemm<3>, cudaFuncAttributeMaxDynamicSharedMemorySize, SM_TOTAL);

    // Weight conversion (transpose + hi/lo split) — per launch, small
    for (int l = 0; l < LAYERS; l++) {
        wconv_kernel<<<dim3(8, 8),  256>>>(Wq + (size_t)l*DDIM*DDIM, wqh + (size_t)l*DDIM*DDIM, wql + (size_t)l*DDIM*DDIM, DDIM, DDIM);
        wconv_kernel<<<dim3(8, 8),  256>>>(Wk + (size_t)l*DDIM*DDIM, wkh + (size_t)l*DDIM*DDIM, wkl + (size_t)l*DDIM*DDIM, DDIM, DDIM);
        wconv_kernel<<<dim3(8, 8),  256>>>(Wv + (size_t)l*DDIM*DDIM, wvh + (size_t)l*DDIM*DDIM, wvl + (size_t)l*DDIM*DDIM, DDIM, DDIM);
        wconv_kernel<<<dim3(32, 8), 256>>>(WU + (size_t)l*DDIM*FFND, wuh + (size_t)l*DDIM*FFND, wul + (size_t)l*DDIM*FFND, DDIM, FFND);
        wconv_kernel<<<dim3(8, 32), 256>>>(WV + (size_t)l*FFND*DDIM, wvh2 + (size_t)l*FFND*DDIM, wvl2 + (size_t)l*FFND*DDIM, FFND, DDIM);
    }

    embed_kernel<<<ROWS, 128>>>(x, gene_emb, inv_freq, h);

    dim3 gQKV(ROWS/128, DDIM/64);   // (256, 4)
    dim3 gUP (ROWS/128, FFND/64);   // (256, 16)

    for (int l = 0; l < LAYERS; l++) {
        ln_bf16_kernel<<<ROWS, 256>>>(h, ln1g + l*DDIM, ln1b + l*DDIM, hnhi, hnlo);
        tc_gemm<1><<<gQKV, 256, SM_TOTAL>>>(hnhi, hnlo, wqh + (size_t)l*DDIM*DDIM, wql + (size_t)l*DDIM*DDIM,
                                            bq + l*DDIM, nullptr, q, nullptr, nullptr, DDIM, DDIM);
        tc_gemm<1><<<gQKV, 256, SM_TOTAL>>>(hnhi, hnlo, wkh + (size_t)l*DDIM*DDIM, wkl + (size_t)l*DDIM*DDIM,
                                            bk + l*DDIM, nullptr, k, nullptr, nullptr, DDIM, DDIM);
        tc_gemm<0><<<gQKV, 256, SM_TOTAL>>>(hnhi, hnlo, wvh + (size_t)l*DDIM*DDIM, wvl + (size_t)l*DDIM*DDIM,
                                            bv + l*DDIM, nullptr, v, nullptr, nullptr, DDIM, DDIM);

        attn_state_kernel <<<BH*NCHUNK, 1024>>>(k, v, stt);
        attn_prefix_kernel<<<BH, 1024>>>(stt);
        attn_out_kernel   <<<BH*NCHUNK, 256>>>(q, k, v, stt, h);

        ln_bf16_kernel<<<ROWS, 256>>>(h, ln2g + l*DDIM, ln2b + l*DDIM, hnhi, hnlo);
        tc_gemm<2><<<gUP, 256, SM_TOTAL>>>(hnhi, hnlo, wuh + (size_t)l*DDIM*FFND, wul + (size_t)l*DDIM*FFND,
                                           bU + l*FFND, nullptr, nullptr, midhi, midlo, FFND, DDIM);
        tc_gemm<3><<<gQKV, 256, SM_TOTAL>>>(midhi, midlo, wvh2 + (size_t)l*FFND*DDIM, wvl2 + (size_t)l*FFND*DDIM,
                                           bV + l*DDIM, h, h, nullptr, nullptr, DDIM, FFND);
    }

    outproj_kernel<<<ROWS/8, 256>>>(h, Wout, bout, out);
}

// round 13
// speedup vs baseline: 4.2382x; 1.0908x over previous
#include <cuda_runtime.h>
#include <cuda_bf16.h>
#include <cstdint>
#include <math.h>

#define BDIM 16
#define GDIM 2048
#define DDIM 256
#define NHEADS 8
#define HEADDIM 32
#define FFND 1024
#define LAYERS 4
#define ROWS (BDIM*GDIM)   // 32768
#define CHUNK 64
#define NCHUNK (GDIM/CHUNK)      // 32
#define BH (BDIM*NHEADS)         // 128
#define STATE_STRIDE 1056        // 32*32 + 32

// ---------------------------------------------------------------------------
// Scratch (device globals; no runtime allocation allowed)
// ---------------------------------------------------------------------------
__device__ float g_h [ROWS*DDIM];
__device__ float g_q [ROWS*DDIM];
__device__ float g_k [ROWS*DDIM];
__device__ float g_v [ROWS*DDIM];
__device__ float g_state[(size_t)BH*NCHUNK*STATE_STRIDE];

__device__ __nv_bfloat16 g_hnhi[ROWS*DDIM],  g_hnlo[ROWS*DDIM];
__device__ __nv_bfloat16 g_midhi[(size_t)ROWS*FFND], g_midlo[(size_t)ROWS*FFND];
// Transposed split weights: [N, K] layout per matrix
__device__ __nv_bfloat16 g_wqh[LAYERS*DDIM*DDIM], g_wql[LAYERS*DDIM*DDIM];
__device__ __nv_bfloat16 g_wkh[LAYERS*DDIM*DDIM], g_wkl[LAYERS*DDIM*DDIM];
__device__ __nv_bfloat16 g_wvh[LAYERS*DDIM*DDIM], g_wvl[LAYERS*DDIM*DDIM];
__device__ __nv_bfloat16 g_wuh[LAYERS*DDIM*FFND], g_wul[LAYERS*DDIM*FFND];
__device__ __nv_bfloat16 g_wvh2[LAYERS*FFND*DDIM], g_wvl2[LAYERS*FFND*DDIM];

// ---------------------------------------------------------------------------
// Warp-level MMA helpers (base sm_103-legal PTX)
// ---------------------------------------------------------------------------
__device__ __forceinline__ uint32_t smem_to_u32(const void* p) {
    uint32_t a;
    asm("{ .reg .u64 t; cvta.to.shared.u64 t, %1; cvt.u32.u64 %0, t; }" : "=r"(a) : "l"(p));
    return a;
}
__device__ __forceinline__ void ldsm4(uint32_t* r, uint32_t addr) {
    asm volatile("ldmatrix.sync.aligned.m8n8.x4.shared.b16 {%0,%1,%2,%3}, [%4];"
        : "=r"(r[0]), "=r"(r[1]), "=r"(r[2]), "=r"(r[3]) : "r"(addr));
}
__device__ __forceinline__ void ldsm2(uint32_t* r, uint32_t addr) {
    asm volatile("ldmatrix.sync.aligned.m8n8.x2.shared.b16 {%0,%1}, [%2];"
        : "=r"(r[0]), "=r"(r[1]) : "r"(addr));
}
__device__ __forceinline__ void mma16816(float* c, const uint32_t* a, const uint32_t* b) {
    asm volatile(
        "mma.sync.aligned.m16n8k16.row.col.f32.bf16.bf16.f32 "
        "{%0,%1,%2,%3}, {%4,%5,%6,%7}, {%8,%9}, {%0,%1,%2,%3};"
        : "+f"(c[0]), "+f"(c[1]), "+f"(c[2]), "+f"(c[3])
        : "r"(a[0]), "r"(a[1]), "r"(a[2]), "r"(a[3]), "r"(b[0]), "r"(b[1]));
}
__device__ __forceinline__ void cpasync16(uint32_t dst, const void* src) {
    asm volatile("cp.async.cg.shared.global [%0], [%1], 16;" :: "r"(dst), "l"(src));
}
#define CP_COMMIT() asm volatile("cp.async.commit_group;" ::: "memory")
#define CP_WAIT(n)  asm volatile("cp.async.wait_group %0;" :: "n"(n) : "memory")

// ---------------------------------------------------------------------------
// Embedding
// ---------------------------------------------------------------------------
__global__ void embed_kernel(const float* __restrict__ x,
                             const float* __restrict__ gene_emb,
                             const float* __restrict__ inv_freq,
                             float* __restrict__ h) {
    int row = blockIdx.x;
    int g   = row % GDIM;
    int i   = threadIdx.x;
    float xv = x[row];
    float fr = xv * inv_freq[i];
    float s, c;
    sincosf(fr, &s, &c);
    if (xv == -10.0f) { s = 0.0f; c = 0.0f; }
    h[row*DDIM + i]       = gene_emb[g*DDIM + i]       + s;
    h[row*DDIM + 128 + i] = gene_emb[g*DDIM + 128 + i] + c;
}

// ---------------------------------------------------------------------------
// LayerNorm -> split bf16 (hi/lo)
// ---------------------------------------------------------------------------
__global__ void ln_bf16_kernel(const float* __restrict__ in,
                               const float* __restrict__ gamma,
                               const float* __restrict__ beta,
                               __nv_bfloat16* __restrict__ ohi,
                               __nv_bfloat16* __restrict__ olo) {
    int row = blockIdx.x;
    int i = threadIdx.x;
    float v = in[row*DDIM + i];
    float s1 = v, s2 = v*v;
    #pragma unroll
    for (int o = 16; o; o >>= 1) {
        s1 += __shfl_xor_sync(0xffffffffu, s1, o);
        s2 += __shfl_xor_sync(0xffffffffu, s2, o);
    }
    __shared__ float r1[8], r2[8];
    if ((i & 31) == 0) { r1[i>>5] = s1; r2[i>>5] = s2; }
    __syncthreads();
    float t1 = 0.f, t2 = 0.f;
    #pragma unroll
    for (int w = 0; w < 8; w++) { t1 += r1[w]; t2 += r2[w]; }
    float m   = t1 * (1.0f/256.0f);
    float var = t2 * (1.0f/256.0f) - m*m;
    float inv = rsqrtf(var + 1e-5f);
    float y = (v - m) * inv * gamma[i] + beta[i];
    __nv_bfloat16 hi = __float2bfloat16(y);
    __nv_bfloat16 lo = __float2bfloat16(y - __bfloat162float(hi));
    ohi[(size_t)row*DDIM + i] = hi;
    olo[(size_t)row*DDIM + i] = lo;
}

// ---------------------------------------------------------------------------
// Weight transpose + split: W[K,N] fp32 -> out[N,K] bf16 hi/lo
// ---------------------------------------------------------------------------
__global__ void wconv_kernel(const float* __restrict__ W,
                             __nv_bfloat16* __restrict__ hi,
                             __nv_bfloat16* __restrict__ lo,
                             int K, int N) {
    __shared__ float t[32][33];
    int nb = blockIdx.x*32, kb = blockIdx.y*32;
    int tx = threadIdx.x & 31, ty = threadIdx.x >> 5;
    #pragma unroll
    for (int j = 0; j < 32; j += 8)
        t[ty+j][tx] = W[(size_t)(kb+ty+j)*N + nb+tx];
    __syncthreads();
    #pragma unroll
    for (int j = 0; j < 32; j += 8) {
        float v = t[tx][ty+j];
        __nv_bfloat16 h = __float2bfloat16(v);
        __nv_bfloat16 l = __float2bfloat16(v - __bfloat162float(h));
        size_t o = (size_t)(nb+ty+j)*K + kb+tx;
        hi[o] = h; lo[o] = l;
    }
}

// ---------------------------------------------------------------------------
// Pipelined warp-MMA split-bf16 GEMM (2-stage cp.async).
// BM=128, BN=64, BK=64; 8 warps (2x4), warp tile 64x16.
// EPI: 0 none(fp32), 1 square(fp32), 2 gelu->bf16 hi/lo, 3 resid add(fp32)
// ---------------------------------------------------------------------------
#define ASTR 72
#define G_SS      55296                 // per-stage bytes
#define G_AHI     0
#define G_ALO     18432
#define G_BHI     36864
#define G_BLO     46080
#define G_SMEM    (2*G_SS)              // 110592

template<int EPI>
__global__ __launch_bounds__(256, 1) void tc_gemm(
    const __nv_bfloat16* __restrict__ Ahi, const __nv_bfloat16* __restrict__ Alo,
    const __nv_bfloat16* __restrict__ Bhi, const __nv_bfloat16* __restrict__ Blo,
    const float* __restrict__ bias, const float* __restrict__ resid,
    float* __restrict__ Cf,
    __nv_bfloat16* __restrict__ Chi, __nv_bfloat16* __restrict__ Clo,
    int N, int K)
{
    extern __shared__ char smem[];
    uint32_t sbase = smem_to_u32(smem);

    int tid  = threadIdx.x;
    int lane = tid & 31;
    int warp = tid >> 5;
    int wm = warp >> 2;
    int wn = warp & 3;
    int bm = blockIdx.x * 128, bn = blockIdx.y * 64;

    float acc[4][2][4];
    #pragma unroll
    for (int mi = 0; mi < 4; mi++)
        #pragma unroll
        for (int ni = 0; ni < 2; ni++)
            #pragma unroll
            for (int e = 0; e < 4; e++) acc[mi][ni][e] = 0.f;

    const int nkt = K >> 6;

    // --- stage loader
    auto issue = [&](int st, int kt) {
        uint32_t sb = sbase + st * G_SS;
        #pragma unroll
        for (int i = tid; i < 1024; i += 256) {
            int r = i >> 3, kc = (i & 7) * 8;
            size_t go = (size_t)(bm + r) * K + kt + kc;
            uint32_t d = sb + (uint32_t)((r*ASTR + kc) * 2);
            cpasync16(d + G_AHI, Ahi + go);
            cpasync16(d + G_ALO, Alo + go);
        }
        #pragma unroll
        for (int i = tid; i < 512; i += 256) {
            int r = i >> 3, kc = (i & 7) * 8;
            size_t go = (size_t)(bn + r) * K + kt + kc;
            uint32_t d = sb + (uint32_t)((r*ASTR + kc) * 2);
            cpasync16(d + G_BHI, Bhi + go);
            cpasync16(d + G_BLO, Blo + go);
        }
    };

    issue(0, 0);
    CP_COMMIT();

    int ar = lane & 15, ac = (lane >> 4) * 8;
    int br = lane & 7,  bc = ((lane >> 3) & 1) * 8;

    for (int it = 0; it < nkt; it++) {
        if (it + 1 < nkt) { issue((it+1) & 1, (it+1) << 6); CP_COMMIT(); CP_WAIT(1); }
        else              { CP_WAIT(0); }
        __syncthreads();
        uint32_t sb = sbase + (it & 1) * G_SS;
        #pragma unroll
        for (int ks = 0; ks < 4; ks++) {
            uint32_t ah[4][4], al[4][4], bh[2][2], bl[2][2];
            #pragma unroll
            for (int mi = 0; mi < 4; mi++) {
                uint32_t ad = sb + (uint32_t)(((wm*64 + mi*16 + ar)*ASTR + ks*16 + ac) * 2);
                ldsm4(ah[mi], ad + G_AHI);
                ldsm4(al[mi], ad + G_ALO);
            }
            #pragma unroll
            for (int ni = 0; ni < 2; ni++) {
                uint32_t bd = sb + (uint32_t)(((wn*16 + ni*8 + br)*ASTR + ks*16 + bc) * 2);
                ldsm2(bh[ni], bd + G_BHI);
                ldsm2(bl[ni], bd + G_BLO);
            }
            #pragma unroll
            for (int mi = 0; mi < 4; mi++)
                #pragma unroll
                for (int ni = 0; ni < 2; ni++) {
                    mma16816(acc[mi][ni], ah[mi], bh[ni]);
                    mma16816(acc[mi][ni], ah[mi], bl[ni]);
                    mma16816(acc[mi][ni], al[mi], bh[ni]);
                }
        }
        __syncthreads();
    }

    // ---- epilogue
    int r0 = lane >> 2, c0 = (lane & 3) * 2;
    #pragma unroll
    for (int mi = 0; mi < 4; mi++) {
        #pragma unroll
        for (int ni = 0; ni < 2; ni++) {
            int col = bn + wn*16 + ni*8 + c0;
            float b0 = __ldg(&bias[col]), b1 = __ldg(&bias[col+1]);
            #pragma unroll
            for (int hrow = 0; hrow < 2; hrow++) {
                int row = bm + wm*64 + mi*16 + r0 + hrow*8;
                float v0 = acc[mi][ni][hrow*2+0] + b0;
                float v1 = acc[mi][ni][hrow*2+1] + b1;
                size_t o = (size_t)row * N + col;
                if (EPI == 1) {
                    float2 ov = {v0*v0, v1*v1};
                    *(float2*)&Cf[o] = ov;
                } else if (EPI == 2) {
                    float gg0 = 0.5f * v0 * (1.0f + erff(v0 * 0.70710678118654752f));
                    float gg1 = 0.5f * v1 * (1.0f + erff(v1 * 0.70710678118654752f));
                    __nv_bfloat16 h0 = __float2bfloat16(gg0);
                    __nv_bfloat16 h1 = __float2bfloat16(gg1);
                    __nv_bfloat162 hv; hv.x = h0; hv.y = h1;
                    __nv_bfloat162 lv;
                    lv.x = __float2bfloat16(gg0 - __bfloat162float(h0));
                    lv.y = __float2bfloat16(gg1 - __bfloat162float(h1));
                    *(__nv_bfloat162*)&Chi[o] = hv;
                    *(__nv_bfloat162*)&Clo[o] = lv;
                } else if (EPI == 3) {
                    float2 rs = *(const float2*)&resid[o];
                    float2 ov = {v0 + rs.x, v1 + rs.y};
                    *(float2*)&Cf[o] = ov;
                } else {
                    float2 ov = {v0, v1};
                    *(float2*)&Cf[o] = ov;
                }
            }
        }
    }
}

// ---------------------------------------------------------------------------
// Fused QKV GEMM: shares the A tile across Q, K, V weight matrices.
// Same tile/warp layout; 3 accumulator sets. Q,K squared; V plain.
// ---------------------------------------------------------------------------
#define Q_SS      92160                 // per-stage: A 36864 + 3*B 18432
#define Q_AHI     0
#define Q_ALO     18432
#define Q_B(m)    (36864 + (m)*18432)   // hi at +0, lo at +9216
#define Q_SMEM    (2*Q_SS)              // 184320

__global__ __launch_bounds__(256, 1) void qkv_gemm(
    const __nv_bfloat16* __restrict__ Ahi, const __nv_bfloat16* __restrict__ Alo,
    const __nv_bfloat16* __restrict__ Wqh, const __nv_bfloat16* __restrict__ Wql,
    const __nv_bfloat16* __restrict__ Wkh, const __nv_bfloat16* __restrict__ Wkl,
    const __nv_bfloat16* __restrict__ Wvh, const __nv_bfloat16* __restrict__ Wvl,
    const float* __restrict__ bq, const float* __restrict__ bk, const float* __restrict__ bv,
    float* __restrict__ Qo, float* __restrict__ Ko, float* __restrict__ Vo)
{
    const int N = DDIM, K = DDIM;
    extern __shared__ char smem[];
    uint32_t sbase = smem_to_u32(smem);

    int tid  = threadIdx.x;
    int lane = tid & 31;
    int warp = tid >> 5;
    int wm = warp >> 2;
    int wn = warp & 3;
    int bm = blockIdx.x * 128, bn = blockIdx.y * 64;

    const __nv_bfloat16* Bh[3] = {Wqh, Wkh, Wvh};
    const __nv_bfloat16* Bl[3] = {Wql, Wkl, Wvl};

    float acc[3][4][2][4];
    #pragma unroll
    for (int m = 0; m < 3; m++)
        #pragma unroll
        for (int mi = 0; mi < 4; mi++)
            #pragma unroll
            for (int ni = 0; ni < 2; ni++)
                #pragma unroll
                for (int e = 0; e < 4; e++) acc[m][mi][ni][e] = 0.f;

    auto issue = [&](int st, int kt) {
        uint32_t sb = sbase + st * Q_SS;
        #pragma unroll
        for (int i = tid; i < 1024; i += 256) {
            int r = i >> 3, kc = (i & 7) * 8;
            size_t go = (size_t)(bm + r) * K + kt + kc;
            uint32_t d = sb + (uint32_t)((r*ASTR + kc) * 2);
            cpasync16(d + Q_AHI, Ahi + go);
            cpasync16(d + Q_ALO, Alo + go);
        }
        #pragma unroll
        for (int m = 0; m < 3; m++) {
            #pragma unroll
            for (int i = tid; i < 512; i += 256) {
                int r = i >> 3, kc = (i & 7) * 8;
                size_t go = (size_t)(bn + r) * K + kt + kc;
                uint32_t d = sb + Q_B(m) + (uint32_t)((r*ASTR + kc) * 2);
                cpasync16(d, Bh[m] + go);
                cpasync16(d + 9216, Bl[m] + go);
            }
        }
    };

    issue(0, 0);
    CP_COMMIT();

    int ar = lane & 15, ac = (lane >> 4) * 8;
    int br = lane & 7,  bc = ((lane >> 3) & 1) * 8;
    const int nkt = K >> 6;   // 4

    for (int it = 0; it < nkt; it++) {
        if (it + 1 < nkt) { issue((it+1) & 1, (it+1) << 6); CP_COMMIT(); CP_WAIT(1); }
        else              { CP_WAIT(0); }
        __syncthreads();
        uint32_t sb = sbase + (it & 1) * Q_SS;
        #pragma unroll
        for (int ks = 0; ks < 4; ks++) {
            uint32_t ah[4][4], al[4][4];
            #pragma unroll
            for (int mi = 0; mi < 4; mi++) {
                uint32_t ad = sb + (uint32_t)(((wm*64 + mi*16 + ar)*ASTR + ks*16 + ac) * 2);
                ldsm4(ah[mi], ad + Q_AHI);
                ldsm4(al[mi], ad + Q_ALO);
            }
            #pragma unroll
            for (int m = 0; m < 3; m++) {
                uint32_t bh[2][2], bl[2][2];
                #pragma unroll
                for (int ni = 0; ni < 2; ni++) {
                    uint32_t bd = sb + Q_B(m) + (uint32_t)(((wn*16 + ni*8 + br)*ASTR + ks*16 + bc) * 2);
                    ldsm2(bh[ni], bd);
                    ldsm2(bl[ni], bd + 9216);
                }
                #pragma unroll
                for (int mi = 0; mi < 4; mi++)
                    #pragma unroll
                    for (int ni = 0; ni < 2; ni++) {
                        mma16816(acc[m][mi][ni], ah[mi], bh[ni]);
                        mma16816(acc[m][mi][ni], ah[mi], bl[ni]);
                        mma16816(acc[m][mi][ni], al[mi], bh[ni]);
                    }
            }
        }
        __syncthreads();
    }

    // ---- epilogue
    const float* bias[3] = {bq, bk, bv};
    float* outp[3] = {Qo, Ko, Vo};
    int r0 = lane >> 2, c0 = (lane & 3) * 2;
    #pragma unroll
    for (int m = 0; m < 3; m++) {
        #pragma unroll
        for (int mi = 0; mi < 4; mi++) {
            #pragma unroll
            for (int ni = 0; ni < 2; ni++) {
                int col = bn + wn*16 + ni*8 + c0;
                float b0 = __ldg(&bias[m][col]), b1 = __ldg(&bias[m][col+1]);
                #pragma unroll
                for (int hrow = 0; hrow < 2; hrow++) {
                    int row = bm + wm*64 + mi*16 + r0 + hrow*8;
                    float v0 = acc[m][mi][ni][hrow*2+0] + b0;
                    float v1 = acc[m][mi][ni][hrow*2+1] + b1;
                    if (m < 2) { v0 = v0*v0; v1 = v1*v1; }
                    float2 ov = {v0, v1};
                    *(float2*)&outp[m][(size_t)row * N + col] = ov;
                }
            }
        }
    }
}

// ---------------------------------------------------------------------------
// Chunked causal linear attention (unchanged)
// ---------------------------------------------------------------------------
__global__ void attn_state_kernel(const float* __restrict__ K,
                                  const float* __restrict__ V,
                                  float* __restrict__ state) {
    int blk = blockIdx.x;
    int bh  = blk >> 5;
    int c   = blk & 31;
    int b = bh >> 3, hh = bh & 7;
    int f = threadIdx.x & 31;
    int d = threadIdx.x >> 5;
    size_t base = ((size_t)(b*GDIM + c*CHUNK))*DDIM + hh*HEADDIM;
    float s = 0.f, ks = 0.f;
    #pragma unroll 4
    for (int t = 0; t < CHUNK; t++) {
        float kf = K[base + f];
        float vd = V[base + d];
        s  = fmaf(kf, vd, s);
        ks += kf;
        base += DDIM;
    }
    float* st = state + (size_t)blk * STATE_STRIDE;
    st[d*32 + f] = s;
    if (d == 0) st[1024 + f] = ks;
}

__global__ void attn_prefix_kernel(float* __restrict__ state) {
    int bh = blockIdx.x;
    float* st = state + (size_t)bh * NCHUNK * STATE_STRIDE;
    for (int e = threadIdx.x; e < STATE_STRIDE; e += blockDim.x) {
        float run = 0.f;
        float* p = st + e;
        #pragma unroll 4
        for (int c = 0; c < NCHUNK; c++) {
            float t = *p;
            *p = run;
            run += t;
            p += STATE_STRIDE;
        }
    }
}

__global__ __launch_bounds__(256) void attn_out_kernel(
        const float* __restrict__ Q,
        const float* __restrict__ K,
        const float* __restrict__ V,
        const float* __restrict__ state,
        float* __restrict__ H) {
    int blk = blockIdx.x;
    int bh  = blk >> 5;
    int c   = blk & 31;
    int b = bh >> 3, hh = bh & 7;

    __shared__ float Qs[CHUNK*33];
    __shared__ float Ks[CHUNK*33];
    __shared__ float Vs[CHUNK*33];
    __shared__ float Sp[32*33];
    __shared__ float kp[32];
    __shared__ float Am[CHUNK*65];
    __shared__ float den[CHUNK];

    int tid  = threadIdx.x;
    int lane = tid & 31;
    int w    = tid >> 5;
    size_t rowbase = ((size_t)(b*GDIM + c*CHUNK))*DDIM + hh*HEADDIM;

    for (int t = w; t < CHUNK; t += 8) {
        size_t g = rowbase + (size_t)t*DDIM + lane;
        Qs[t*33 + lane] = Q[g];
        Ks[t*33 + lane] = K[g];
        Vs[t*33 + lane] = V[g];
    }
    const float* st = state + (size_t)blk * STATE_STRIDE;
    for (int e = tid; e < 1024; e += 256)
        Sp[(e & 31)*33 + (e >> 5)] = st[e];
    if (tid < 32) kp[tid] = st[1024 + tid];
    __syncthreads();

    {
        int tt = (tid >> 4) << 2;
        int ss = (tid & 15) << 2;
        float acc[4][4];
        #pragma unroll
        for (int i = 0; i < 4; i++)
            #pragma unroll
            for (int j = 0; j < 4; j++) acc[i][j] = 0.f;
        for (int f = 0; f < 32; f++) {
            float qv[4], kv[4];
            #pragma unroll
            for (int i = 0; i < 4; i++) qv[i] = Qs[(tt+i)*33 + f];
            #pragma unroll
            for (int j = 0; j < 4; j++) kv[j] = Ks[(ss+j)*33 + f];
            #pragma unroll
            for (int i = 0; i < 4; i++)
                #pragma unroll
                for (int j = 0; j < 4; j++)
                    acc[i][j] = fmaf(qv[i], kv[j], acc[i][j]);
        }
        #pragma unroll
        for (int i = 0; i < 4; i++)
            #pragma unroll
            for (int j = 0; j < 4; j++)
                Am[(tt+i)*65 + ss+j] = (ss+j <= tt+i) ? acc[i][j] : 0.f;
    }
    __syncthreads();

    if (tid < CHUNK) {
        float s = 0.f;
        for (int ss = 0; ss <= tid; ss++) s += Am[tid*65 + ss];
        for (int f = 0; f < 32; f++) s += Qs[tid*33 + f] * kp[f];
        den[tid] = s + 1e-16f;
    }
    __syncthreads();

    int d = lane;
    float acc[8];
    #pragma unroll
    for (int i = 0; i < 8; i++) acc[i] = 0.f;
    for (int f = 0; f < 32; f++) {
        float sp = Sp[f*33 + d];
        #pragma unroll
        for (int i = 0; i < 8; i++)
            acc[i] = fmaf(Qs[(w*8+i)*33 + f], sp, acc[i]);
    }
    for (int s = 0; s < CHUNK; s++) {
        float vv = Vs[s*33 + d];
        #pragma unroll
        for (int i = 0; i < 8; i++)
            acc[i] = fmaf(Am[(w*8+i)*65 + s], vv, acc[i]);
    }
    #pragma unroll
    for (int i = 0; i < 8; i++) {
        int t = w*8 + i;
        H[rowbase + (size_t)t*DDIM + d] += acc[i] / den[t];
    }
}

// ---------------------------------------------------------------------------
// Output projection
// ---------------------------------------------------------------------------
__global__ void outproj_kernel(const float* __restrict__ H,
                               const float* __restrict__ Wout,
                               const float* __restrict__ bout,
                               float* __restrict__ out) {
    int row  = blockIdx.x * 8 + (threadIdx.x >> 5);
    int lane = threadIdx.x & 31;
    float s = 0.f;
    #pragma unroll
    for (int i = 0; i < 8; i++) {
        int c = lane + i*32;
        s += H[(size_t)row*DDIM + c] * Wout[c];
    }
    #pragma unroll
    for (int o = 16; o; o >>= 1) s += __shfl_xor_sync(0xffffffffu, s, o);
    if (lane == 0) out[row] = s + bout[0];
}

// ---------------------------------------------------------------------------
extern "C" void kernel_launch(void* const* d_in, const int* in_sizes, int n_in,
                              void* d_out, int out_size) {
    const float* x        = (const float*)d_in[0];
    const float* gene_emb = (const float*)d_in[1];
    const float* inv_freq = (const float*)d_in[2];
    const float* Wq   = (const float*)d_in[3];
    const float* bq   = (const float*)d_in[4];
    const float* Wk   = (const float*)d_in[5];
    const float* bk   = (const float*)d_in[6];
    const float* Wv   = (const float*)d_in[7];
    const float* bv   = (const float*)d_in[8];
    const float* ln1g = (const float*)d_in[9];
    const float* ln1b = (const float*)d_in[10];
    const float* ln2g = (const float*)d_in[11];
    const float* ln2b = (const float*)d_in[12];
    const float* WU   = (const float*)d_in[13];
    const float* bU   = (const float*)d_in[14];
    const float* WV   = (const float*)d_in[15];
    const float* bV   = (const float*)d_in[16];
    const float* Wout = (const float*)d_in[17];
    const float* bout = (const float*)d_in[18];
    float* out = (float*)d_out;

    float *h, *q, *k, *v, *stt;
    cudaGetSymbolAddress((void**)&h,   g_h);
    cudaGetSymbolAddress((void**)&q,   g_q);
    cudaGetSymbolAddress((void**)&k,   g_k);
    cudaGetSymbolAddress((void**)&v,   g_v);
    cudaGetSymbolAddress((void**)&stt, g_state);

    __nv_bfloat16 *hnhi, *hnlo, *midhi, *midlo;
    __nv_bfloat16 *wqh, *wql, *wkh, *wkl, *wvh, *wvl, *wuh, *wul, *wvh2, *wvl2;
    cudaGetSymbolAddress((void**)&hnhi,  g_hnhi);
    cudaGetSymbolAddress((void**)&hnlo,  g_hnlo);
    cudaGetSymbolAddress((void**)&midhi, g_midhi);
    cudaGetSymbolAddress((void**)&midlo, g_midlo);
    cudaGetSymbolAddress((void**)&wqh,  g_wqh);
    cudaGetSymbolAddress((void**)&wql,  g_wql);
    cudaGetSymbolAddress((void**)&wkh,  g_wkh);
    cudaGetSymbolAddress((void**)&wkl,  g_wkl);
    cudaGetSymbolAddress((void**)&wvh,  g_wvh);
    cudaGetSymbolAddress((void**)&wvl,  g_wvl);
    cudaGetSymbolAddress((void**)&wuh,  g_wuh);
    cudaGetSymbolAddress((void**)&wul,  g_wul);
    cudaGetSymbolAddress((void**)&wvh2, g_wvh2);
    cudaGetSymbolAddress((void**)&wvl2, g_wvl2);

    cudaFuncSetAttribute(tc_gemm<2>, cudaFuncAttributeMaxDynamicSharedMemorySize, G_SMEM);
    cudaFuncSetAttribute(tc_gemm<3>, cudaFuncAttributeMaxDynamicSharedMemorySize, G_SMEM);
    cudaFuncSetAttribute(qkv_gemm,   cudaFuncAttributeMaxDynamicSharedMemorySize, Q_SMEM);

    // Weight conversion (transpose + hi/lo split)
    for (int l = 0; l < LAYERS; l++) {
        wconv_kernel<<<dim3(8, 8),  256>>>(Wq + (size_t)l*DDIM*DDIM, wqh + (size_t)l*DDIM*DDIM, wql + (size_t)l*DDIM*DDIM, DDIM, DDIM);
        wconv_kernel<<<dim3(8, 8),  256>>>(Wk + (size_t)l*DDIM*DDIM, wkh + (size_t)l*DDIM*DDIM, wkl + (size_t)l*DDIM*DDIM, DDIM, DDIM);
        wconv_kernel<<<dim3(8, 8),  256>>>(Wv + (size_t)l*DDIM*DDIM, wvh + (size_t)l*DDIM*DDIM, wvl + (size_t)l*DDIM*DDIM, DDIM, DDIM);
        wconv_kernel<<<dim3(32, 8), 256>>>(WU + (size_t)l*DDIM*FFND, wuh + (size_t)l*DDIM*FFND, wul + (size_t)l*DDIM*FFND, DDIM, FFND);
        wconv_kernel<<<dim3(8, 32), 256>>>(WV + (size_t)l*FFND*DDIM, wvh2 + (size_t)l*FFND*DDIM, wvl2 + (size_t)l*FFND*DDIM, FFND, DDIM);
    }

    embed_kernel<<<ROWS, 128>>>(x, gene_emb, inv_freq, h);

    dim3 gQKV(ROWS/128, DDIM/64);   // (256, 4)
    dim3 gUP (ROWS/128, FFND/64);   // (256, 16)

    for (int l = 0; l < LAYERS; l++) {
        ln_bf16_kernel<<<ROWS, 256>>>(h, ln1g + l*DDIM, ln1b + l*DDIM, hnhi, hnlo);
        qkv_gemm<<<gQKV, 256, Q_SMEM>>>(hnhi, hnlo,
            wqh + (size_t)l*DDIM*DDIM, wql + (size_t)l*DDIM*DDIM,
            wkh + (size_t)l*DDIM*DDIM, wkl + (size_t)l*DDIM*DDIM,
            wvh + (size_t)l*DDIM*DDIM, wvl + (size_t)l*DDIM*DDIM,
            bq + l*DDIM, bk + l*DDIM, bv + l*DDIM, q, k, v);

        attn_state_kernel <<<BH*NCHUNK, 1024>>>(k, v, stt);
        attn_prefix_kernel<<<BH, 1024>>>(stt);
        attn_out_kernel   <<<BH*NCHUNK, 256>>>(q, k, v, stt, h);

        ln_bf16_kernel<<<ROWS, 256>>>(h, ln2g + l*DDIM, ln2b + l*DDIM, hnhi, hnlo);
        tc_gemm<2><<<gUP, 256, G_SMEM>>>(hnhi, hnlo, wuh + (size_t)l*DDIM*FFND, wul + (size_t)l*DDIM*FFND,
                                         bU + l*FFND, nullptr, nullptr, midhi, midlo, FFND, DDIM);
        tc_gemm<3><<<gQKV, 256, G_SMEM>>>(midhi, midlo, wvh2 + (size_t)l*FFND*DDIM, wvl2 + (size_t)l*FFND*DDIM,
                                          bV + l*DDIM, h, h, nullptr, nullptr, DDIM, FFND);
    }

    outproj_kernel<<<ROWS/8, 256>>>(h, Wout, bout, out);
}